// round 9
// baseline (speedup 1.0000x reference)
#include <cuda_runtime.h>
#include <cuda_fp16.h>
#include <math.h>

#define NB 128
#define NH 256
#define NW 256
#define NC 64
#define GS 273    // float2 stride per transpose group (16*17 + 1) — conflict-free

// 128*256*256 complex half = 32 MB static scratch (allocation-free).
// W-dimension stored DIGIT-SWAPPED: position p = k2*16 + k1 holds spectrum
// index kw = 16*k1 + k2. Pass 1 writes it contiguously, pass 3 reads it
// contiguously, pass 2 is agnostic (per-column) except for the mask index.
__device__ __half2 g_scratch[(size_t)NB * NH * NW];

__device__ __forceinline__ float2 cadd(float2 a, float2 b){ return make_float2(a.x+b.x, a.y+b.y); }
__device__ __forceinline__ float2 csub(float2 a, float2 b){ return make_float2(a.x-b.x, a.y-b.y); }
__device__ __forceinline__ float2 cmul(float2 a, float2 b){
    return make_float2(fmaf(a.x, b.x, -a.y*b.y), fmaf(a.x, b.y, a.y*b.x));
}
template<int SIGN>
__device__ __forceinline__ float2 rot90(float2 a){   // × (-i) fwd, (+i) inv
    return (SIGN < 0) ? make_float2(a.y, -a.x) : make_float2(-a.y, a.x);
}
template<int SIGN>
__device__ __forceinline__ float2 cmulw(float2 a, float wr, float wi_f){
    float wi = (SIGN < 0) ? wi_f : -wi_f;
    return make_float2(fmaf(a.x, wr, -a.y*wi), fmaf(a.x, wi, a.y*wr));
}
__device__ __forceinline__ __half2 f2h(float2 v){ return __float22half2_rn(v); }
__device__ __forceinline__ float2 h2f(__half2 v){ return __half22float2(v); }

// Fully-unrolled 16-point DFT in registers, all twiddles as immediates.
template<int SIGN>
__device__ __forceinline__ void fft16(float2* r){
    const float C1 = 0.92387953251f, S1 = 0.38268343236f, C2 = 0.70710678119f;
    float2 v[16];
#pragma unroll
    for (int p = 0; p < 4; ++p){
        float2 a=r[p], b=r[p+4], c=r[p+8], d=r[p+12];
        float2 t0=cadd(a,c), t1=csub(a,c), t2=cadd(b,d);
        float2 t3=rot90<SIGN>(csub(b,d));
        float2 u0=cadd(t0,t2), u1=cadd(t1,t3), u2=csub(t0,t2), u3=csub(t1,t3);
        if (p == 1){
            u1 = cmulw<SIGN>(u1,  C1, -S1);
            u2 = cmulw<SIGN>(u2,  C2, -C2);
            u3 = cmulw<SIGN>(u3,  S1, -C1);
        } else if (p == 2){
            u1 = cmulw<SIGN>(u1,  C2, -C2);
            u2 = rot90<SIGN>(u2);
            u3 = cmulw<SIGN>(u3, -C2, -C2);
        } else if (p == 3){
            u1 = cmulw<SIGN>(u1,  S1, -C1);
            u2 = cmulw<SIGN>(u2, -C2, -C2);
            u3 = cmulw<SIGN>(u3, -C1,  S1);
        }
        v[p]=u0; v[4+p]=u1; v[8+p]=u2; v[12+p]=u3;
    }
#pragma unroll
    for (int m = 0; m < 4; ++m){
        float2 a=v[4*m], b=v[4*m+1], c=v[4*m+2], d=v[4*m+3];
        float2 t0=cadd(a,c), t1=csub(a,c), t2=cadd(b,d);
        float2 t3=rot90<SIGN>(csub(b,d));
        r[m]    = cadd(t0,t2);
        r[4+m]  = cadd(t1,t3);
        r[8+m]  = csub(t0,t2);
        r[12+m] = csub(t1,t3);
    }
}

// r[k] *= w^k, w = exp(SIGN*2*pi*i*n1/256), via log-depth power tree (depth 4).
template<int SIGN>
__device__ __forceinline__ void twiddle_pows(float2* r, int n1){
    float sn, cs;
    sincospif((float)n1 * (1.0f/128.0f), &sn, &cs);
    float2 w1 = make_float2(cs, (SIGN < 0) ? -sn : sn);
    float2 w2  = cmul(w1, w1);
    float2 w3  = cmul(w1, w2);
    float2 w4  = cmul(w2, w2);
    float2 w5  = cmul(w1, w4);
    float2 w6  = cmul(w3, w3);
    float2 w7  = cmul(w3, w4);
    float2 w8  = cmul(w4, w4);
    r[1] = cmul(r[1], w1);  r[2] = cmul(r[2], w2);
    r[3] = cmul(r[3], w3);  r[4] = cmul(r[4], w4);
    r[5] = cmul(r[5], w5);  r[6] = cmul(r[6], w6);
    r[7] = cmul(r[7], w7);  r[8] = cmul(r[8], w8);
    r[9]  = cmul(r[9],  cmul(w1, w8));
    r[10] = cmul(r[10], cmul(w2, w8));
    r[11] = cmul(r[11], cmul(w3, w8));
    r[12] = cmul(r[12], cmul(w4, w8));
    r[13] = cmul(r[13], cmul(w5, w8));
    r[14] = cmul(r[14], cmul(w6, w8));
    r[15] = cmul(r[15], cmul(w7, w8));
}

// ---------------------------------------------------------------------------
// Pass 1: forward FFT along W. 16 rows/block, 256 threads. No block barriers.
// Output digit-swapped -> contiguous 64B per thread -> 4x STG.128.
// ---------------------------------------------------------------------------
__global__ void __launch_bounds__(256) k_rowfft(const float* __restrict__ x){
    __shared__ float2 s[16*GS];
    int t = threadIdx.x;
    int n1 = t & 15, wl = t >> 4;
    int row = blockIdx.x * 16 + wl;
    const float* xr = x + (size_t)row * NW;
    float2 r[16];
#pragma unroll
    for (int n2 = 0; n2 < 16; ++n2) r[n2] = make_float2(xr[n1 + 16*n2], 0.0f);
    fft16<-1>(r);                         // over n2 -> regs k2
    twiddle_pows<-1>(r, n1);
    float2* sg = s + wl*GS;
#pragma unroll
    for (int k2 = 0; k2 < 16; ++k2) sg[n1*17 + k2] = r[k2];
    __syncwarp();
#pragma unroll
    for (int i = 0; i < 16; ++i) r[i] = sg[i*17 + n1];   // thread role: k2 = n1
    fft16<-1>(r);                         // over n1 -> regs k1: X[16*k1 + n1]
    // digit-swapped store: p = n1*16 + k1 -> contiguous 16 half2 = 64B
    __half2 hb[16];
#pragma unroll
    for (int k1 = 0; k1 < 16; ++k1) hb[k1] = f2h(r[k1]);
    uint4* dst = reinterpret_cast<uint4*>(g_scratch + (size_t)row * NW + n1*16);
    const uint4* src = reinterpret_cast<const uint4*>(hb);
#pragma unroll
    for (int i = 0; i < 4; ++i) dst[i] = src[i];
}

// ---------------------------------------------------------------------------
// Pass 2: fwd FFT along H + mask (fftshift folded) + inv FFT along H (×1/256),
// fused. Block = (batch b, 16-p-column tile). thread: w = t&15, u = t>>4.
// True frequency index of p-column (p0 + w): kw = 16*w + blockIdx.x.
// ---------------------------------------------------------------------------
__global__ void __launch_bounds__(256) k_colfft_mask(const float* __restrict__ pi,
                                                     const int* __restrict__ cid){
    __shared__ float2 s[16*GS];
    __shared__ float sPI[NC];
    int t = threadIdx.x;
    int b  = blockIdx.y;
    int bx = blockIdx.x;
    int p0 = bx * 16;
    if (t < NC) sPI[t] = pi[((b + 64) & 127) * NC + t];
    int w = t & 15, u = t >> 4;
    __half2* g = g_scratch + (size_t)b * NH * NW + p0;
    float2 r[16];
#pragma unroll
    for (int n2 = 0; n2 < 16; ++n2) r[n2] = h2f(g[(u + 16*n2)*NW + w]);
    // hoisted cid loads; kw of this thread's column = 16*w + bx
    int wp = (16*w + bx + 128) & 255;
    int cc[16];
#pragma unroll
    for (int k1 = 0; k1 < 16; ++k1){
        int hp = (16*k1 + u + 128) & 255;
        cc[k1] = __ldg(&cid[hp*NW + wp]);
    }
    fft16<-1>(r);                         // over n2 -> k2
    twiddle_pows<-1>(r, u);
    float2* sg = s + w*GS;
#pragma unroll
    for (int k2 = 0; k2 < 16; ++k2) sg[u*17 + k2] = r[k2];
    __syncthreads();                      // also covers sPI writes
#pragma unroll
    for (int i = 0; i < 16; ++i) r[i] = sg[i*17 + u];    // thread role: k2 = u
    fft16<-1>(r);                         // over n1 -> k1: F[16*k1 + u]
#pragma unroll
    for (int k1 = 0; k1 < 16; ++k1){
        float m = (cc[k1] < NC) ? sPI[cc[k1]] : 1.0f;
        r[k1].x *= m; r[k1].y *= m;
    }
    fft16<1>(r);                          // over k1 -> m1
    twiddle_pows<1>(r, u);
    __syncthreads();
#pragma unroll
    for (int m1 = 0; m1 < 16; ++m1) sg[u*17 + m1] = r[m1];
    __syncthreads();
#pragma unroll
    for (int i = 0; i < 16; ++i) r[i] = sg[i*17 + u];    // thread role: m1 = u
    fft16<1>(r);                          // over k2 -> m2: y[m1 + 16*m2]
    const float inv256 = 1.0f / 256.0f;
#pragma unroll
    for (int m2 = 0; m2 < 16; ++m2)
        g[(u + 16*m2)*NW + w] = f2h(make_float2(r[m2].x * inv256, r[m2].y * inv256));
}

// ---------------------------------------------------------------------------
// Pass 3: inverse FFT along W (remaining 1/256) + magnitude + 3 channels + pi.
// Digit-swapped scratch -> thread u loads 64B contiguous -> 4x LDG.128.
// ---------------------------------------------------------------------------
__global__ void __launch_bounds__(256) k_irow_out(const float* __restrict__ x,
                                                  const float* __restrict__ pi,
                                                  float* __restrict__ out){
    __shared__ float2 s[16*GS];
    int t = threadIdx.x;
    int u = t & 15, rl = t >> 4;
    int row = blockIdx.x * 16 + rl;
    int b = row >> 8, h = row & 255;
    // p = u*16 + k1 holds kw = 16*k1 + u -> exactly thread u's needed set, contiguous
    uint4 buf[4];
    const uint4* srcv = reinterpret_cast<const uint4*>(g_scratch + (size_t)row * NW + u*16);
#pragma unroll
    for (int i = 0; i < 4; ++i) buf[i] = srcv[i];
    const __half2* hb = reinterpret_cast<const __half2*>(buf);
    float2 r[16];
#pragma unroll
    for (int k1 = 0; k1 < 16; ++k1) r[k1] = h2f(hb[k1]);
    fft16<1>(r);                          // over k1 -> m1
    twiddle_pows<1>(r, u);
    float2* sg = s + rl*GS;
#pragma unroll
    for (int m1 = 0; m1 < 16; ++m1) sg[u*17 + m1] = r[m1];
    __syncwarp();
#pragma unroll
    for (int i = 0; i < 16; ++i) r[i] = sg[i*17 + u];    // thread role: m1 = u
    fft16<1>(r);                          // over k2 -> m2: y[u + 16*m2]
    const float sc = 1.0f / 256.0f;       // second half of 1/65536
    const float* xr = x + (size_t)row * NW;
    size_t base = ((size_t)(b*3) * NH + h) * NW;
#pragma unroll
    for (int m2 = 0; m2 < 16; ++m2){
        int m = u + 16*m2;
        float2 v = r[m2];
        float mag = sqrtf(fmaf(v.x, v.x, v.y*v.y)) * sc;
        float xv = xr[m];
        out[base + m]                      = xv;
        out[base + (size_t)NH*NW + m]      = mag;
        out[base + 2*(size_t)NH*NW + m]    = fabsf(mag - xv);
    }
    if (blockIdx.x == 0){
        for (int i = t; i < NB * NC; i += 256)
            out[(size_t)NB * 3 * NH * NW + i] = pi[i];
    }
}

extern "C" void kernel_launch(void* const* d_in, const int* in_sizes, int n_in,
                              void* d_out, int out_size) {
    const float* x  = (const float*)d_in[0];   // [128,256,256] f32
    const float* pi = (const float*)d_in[1];   // [128,64]      f32
    const int* cid  = (const int*)d_in[2];     // [256,256]     i32
    float* out = (float*)d_out;                // [128,3,256,256] + [128,64]

    k_rowfft<<<(NB*NH)/16, 256>>>(x);
    k_colfft_mask<<<dim3(NW/16, NB), 256>>>(pi, cid);
    k_irow_out<<<(NB*NH)/16, 256>>>(x, pi, out);
}

// round 10
// speedup vs baseline: 1.7277x; 1.7277x over previous
#include <cuda_runtime.h>
#include <cuda_fp16.h>
#include <math.h>

#define NB 128
#define NH 256
#define NW 256
#define NC 64
#define GS 273    // float2 stride per transpose group (16*17 + 1) — conflict-free

// Pass-1 output: only kw = 0..128 valid (Hermitian half, x real). 32 MB.
__device__ __half2 g_scratch [(size_t)NB * NH * NW];
// Pass-2 output (full width) -> read by pass 3. Separate buffer avoids the
// cross-block race created by mirror reads. 32 MB.
__device__ __half2 g_scratch2[(size_t)NB * NH * NW];

__device__ __forceinline__ float2 cadd(float2 a, float2 b){ return make_float2(a.x+b.x, a.y+b.y); }
__device__ __forceinline__ float2 csub(float2 a, float2 b){ return make_float2(a.x-b.x, a.y-b.y); }
__device__ __forceinline__ float2 cmul(float2 a, float2 b){
    return make_float2(fmaf(a.x, b.x, -a.y*b.y), fmaf(a.x, b.y, a.y*b.x));
}
template<int SIGN>
__device__ __forceinline__ float2 rot90(float2 a){   // × (-i) fwd, (+i) inv
    return (SIGN < 0) ? make_float2(a.y, -a.x) : make_float2(-a.y, a.x);
}
template<int SIGN>
__device__ __forceinline__ float2 cmulw(float2 a, float wr, float wi_f){
    float wi = (SIGN < 0) ? wi_f : -wi_f;
    return make_float2(fmaf(a.x, wr, -a.y*wi), fmaf(a.x, wi, a.y*wr));
}
__device__ __forceinline__ __half2 f2h(float2 v){ return __float22half2_rn(v); }
__device__ __forceinline__ float2 h2f(__half2 v){ return __half22float2(v); }

// Fully-unrolled 16-point DFT in registers, all twiddles as immediates.
template<int SIGN>
__device__ __forceinline__ void fft16(float2* r){
    const float C1 = 0.92387953251f, S1 = 0.38268343236f, C2 = 0.70710678119f;
    float2 v[16];
#pragma unroll
    for (int p = 0; p < 4; ++p){
        float2 a=r[p], b=r[p+4], c=r[p+8], d=r[p+12];
        float2 t0=cadd(a,c), t1=csub(a,c), t2=cadd(b,d);
        float2 t3=rot90<SIGN>(csub(b,d));
        float2 u0=cadd(t0,t2), u1=cadd(t1,t3), u2=csub(t0,t2), u3=csub(t1,t3);
        if (p == 1){
            u1 = cmulw<SIGN>(u1,  C1, -S1);
            u2 = cmulw<SIGN>(u2,  C2, -C2);
            u3 = cmulw<SIGN>(u3,  S1, -C1);
        } else if (p == 2){
            u1 = cmulw<SIGN>(u1,  C2, -C2);
            u2 = rot90<SIGN>(u2);
            u3 = cmulw<SIGN>(u3, -C2, -C2);
        } else if (p == 3){
            u1 = cmulw<SIGN>(u1,  S1, -C1);
            u2 = cmulw<SIGN>(u2, -C2, -C2);
            u3 = cmulw<SIGN>(u3, -C1,  S1);
        }
        v[p]=u0; v[4+p]=u1; v[8+p]=u2; v[12+p]=u3;
    }
#pragma unroll
    for (int m = 0; m < 4; ++m){
        float2 a=v[4*m], b=v[4*m+1], c=v[4*m+2], d=v[4*m+3];
        float2 t0=cadd(a,c), t1=csub(a,c), t2=cadd(b,d);
        float2 t3=rot90<SIGN>(csub(b,d));
        r[m]    = cadd(t0,t2);
        r[4+m]  = cadd(t1,t3);
        r[8+m]  = csub(t0,t2);
        r[12+m] = csub(t1,t3);
    }
}

// r[k] *= w^k, w = exp(SIGN*2*pi*i*n1/256). MUFU base + serial power chain.
template<int SIGN>
__device__ __forceinline__ void twiddle_pows(float2* r, int n1){
    float sn, cs;
    __sincosf((float)n1 * 0.024543692606170259f /* pi/128 */, &sn, &cs);
    float2 w = make_float2(cs, (SIGN < 0) ? -sn : sn);
    float2 acc = w;
    r[1] = cmul(r[1], acc);
#pragma unroll
    for (int k = 2; k < 16; ++k){
        acc = cmul(acc, w);
        r[k] = cmul(r[k], acc);
    }
}

// ---------------------------------------------------------------------------
// Pass 1: forward FFT along W. 16 rows/block, 256 threads. No block barriers.
// Hermitian half-store: only kw <= 128 written (x real).
// ---------------------------------------------------------------------------
__global__ void __launch_bounds__(256) k_rowfft(const float* __restrict__ x){
    __shared__ float2 s[16*GS];
    int t = threadIdx.x;
    int n1 = t & 15, wl = t >> 4;
    int row = blockIdx.x * 16 + wl;
    const float* xr = x + (size_t)row * NW;
    float2 r[16];
#pragma unroll
    for (int n2 = 0; n2 < 16; ++n2) r[n2] = make_float2(xr[n1 + 16*n2], 0.0f);
    fft16<-1>(r);                         // over n2 -> regs k2
    twiddle_pows<-1>(r, n1);
    float2* sg = s + wl*GS;
#pragma unroll
    for (int k2 = 0; k2 < 16; ++k2) sg[n1*17 + k2] = r[k2];
    __syncwarp();
#pragma unroll
    for (int i = 0; i < 16; ++i) r[i] = sg[i*17 + n1];   // thread role: k2 = n1
    fft16<-1>(r);                         // over n1 -> regs k1: X[16*k1 + n1]
    __half2* gp = g_scratch + (size_t)row * NW;
#pragma unroll
    for (int k1 = 0; k1 < 16; ++k1){
        int kw = 16*k1 + n1;
        if (kw <= 128) gp[kw] = f2h(r[k1]);
    }
}

// ---------------------------------------------------------------------------
// Pass 2: fwd FFT along H + mask (fftshift folded) + inv FFT along H (×1/256),
// fused. Block = (batch b, 16-column tile). thread: w = t&15, u = t>>4.
// Columns kw > 128 are reconstructed from the mirror column via conjugation
// (Hermitian along w, pre-H-FFT). Reads g_scratch, writes g_scratch2.
// ---------------------------------------------------------------------------
__global__ void __launch_bounds__(256) k_colfft_mask(const float* __restrict__ pi,
                                                     const int* __restrict__ cid){
    __shared__ float2 s[16*GS];
    __shared__ float sPI[NC];
    int t = threadIdx.x;
    int b  = blockIdx.y;
    int w0 = blockIdx.x * 16;
    if (t < NC) sPI[t] = pi[((b + 64) & 127) * NC + t];
    int w = t & 15, u = t >> 4;
    int wk = w0 + w;                       // true spectral column
    int srcw = (wk <= 128) ? wk : 256 - wk;
    float cj = (wk <= 128) ? 1.0f : -1.0f;
    const __half2* gin = g_scratch + (size_t)b * NH * NW;
    __half2* gout = g_scratch2 + (size_t)b * NH * NW;
    float2 r[16];
#pragma unroll
    for (int n2 = 0; n2 < 16; ++n2){
        float2 v = h2f(gin[(u + 16*n2)*NW + srcw]);
        v.y *= cj;
        r[n2] = v;
    }
    // hoisted cid loads
    int wp = (wk + 128) & 255;
    int cc[16];
#pragma unroll
    for (int k1 = 0; k1 < 16; ++k1){
        int hp = (16*k1 + u + 128) & 255;
        cc[k1] = __ldg(&cid[hp*NW + wp]);
    }
    fft16<-1>(r);                         // over n2 -> k2
    twiddle_pows<-1>(r, u);
    float2* sg = s + w*GS;
#pragma unroll
    for (int k2 = 0; k2 < 16; ++k2) sg[u*17 + k2] = r[k2];
    __syncthreads();                      // also covers sPI writes
#pragma unroll
    for (int i = 0; i < 16; ++i) r[i] = sg[i*17 + u];    // thread role: k2 = u
    fft16<-1>(r);                         // over n1 -> k1: F[16*k1 + u]
#pragma unroll
    for (int k1 = 0; k1 < 16; ++k1){
        float m = (cc[k1] < NC) ? sPI[cc[k1]] : 1.0f;
        r[k1].x *= m; r[k1].y *= m;
    }
    fft16<1>(r);                          // over k1 -> m1
    twiddle_pows<1>(r, u);
    __syncthreads();
#pragma unroll
    for (int m1 = 0; m1 < 16; ++m1) sg[u*17 + m1] = r[m1];
    __syncthreads();
#pragma unroll
    for (int i = 0; i < 16; ++i) r[i] = sg[i*17 + u];    // thread role: m1 = u
    fft16<1>(r);                          // over k2 -> m2: y[m1 + 16*m2]
    const float inv256 = 1.0f / 256.0f;
#pragma unroll
    for (int m2 = 0; m2 < 16; ++m2)
        gout[(u + 16*m2)*NW + wk] = f2h(make_float2(r[m2].x * inv256, r[m2].y * inv256));
}

// ---------------------------------------------------------------------------
// Pass 3: inverse FFT along W (remaining 1/256) + magnitude + 3 channels + pi.
// Reads g_scratch2.
// ---------------------------------------------------------------------------
__global__ void __launch_bounds__(256) k_irow_out(const float* __restrict__ x,
                                                  const float* __restrict__ pi,
                                                  float* __restrict__ out){
    __shared__ float2 s[16*GS];
    int t = threadIdx.x;
    int u = t & 15, rl = t >> 4;
    int row = blockIdx.x * 16 + rl;
    int b = row >> 8, h = row & 255;
    const __half2* gp = g_scratch2 + (size_t)row * NW;
    float2 r[16];
#pragma unroll
    for (int k1 = 0; k1 < 16; ++k1) r[k1] = h2f(gp[u + 16*k1]);
    fft16<1>(r);                          // over k1 -> m1
    twiddle_pows<1>(r, u);
    float2* sg = s + rl*GS;
#pragma unroll
    for (int m1 = 0; m1 < 16; ++m1) sg[u*17 + m1] = r[m1];
    __syncwarp();
#pragma unroll
    for (int i = 0; i < 16; ++i) r[i] = sg[i*17 + u];    // thread role: m1 = u
    fft16<1>(r);                          // over k2 -> m2: y[u + 16*m2]
    const float sc = 1.0f / 256.0f;       // second half of 1/65536
    const float* xr = x + (size_t)row * NW;
    size_t base = ((size_t)(b*3) * NH + h) * NW;
#pragma unroll
    for (int m2 = 0; m2 < 16; ++m2){
        int m = u + 16*m2;
        float2 v = r[m2];
        float mag = sqrtf(fmaf(v.x, v.x, v.y*v.y)) * sc;
        float xv = xr[m];
        out[base + m]                      = xv;
        out[base + (size_t)NH*NW + m]      = mag;
        out[base + 2*(size_t)NH*NW + m]    = fabsf(mag - xv);
    }
    if (blockIdx.x == 0){
        for (int i = t; i < NB * NC; i += 256)
            out[(size_t)NB * 3 * NH * NW + i] = pi[i];
    }
}

extern "C" void kernel_launch(void* const* d_in, const int* in_sizes, int n_in,
                              void* d_out, int out_size) {
    const float* x  = (const float*)d_in[0];   // [128,256,256] f32
    const float* pi = (const float*)d_in[1];   // [128,64]      f32
    const int* cid  = (const int*)d_in[2];     // [256,256]     i32
    float* out = (float*)d_out;                // [128,3,256,256] + [128,64]

    k_rowfft<<<(NB*NH)/16, 256>>>(x);
    k_colfft_mask<<<dim3(NW/16, NB), 256>>>(pi, cid);
    k_irow_out<<<(NB*NH)/16, 256>>>(x, pi, out);
}

// round 11
// speedup vs baseline: 1.8393x; 1.0646x over previous
#include <cuda_runtime.h>
#include <cuda_fp16.h>
#include <math.h>

#define NB 128
#define NH 256
#define NW 256
#define NC 64
#define GS 273    // float2 stride per transpose group (16*17 + 1) — conflict-free

// 128*256*256 complex half = 32 MB static scratch (allocation-free)
__device__ __half2 g_scratch[(size_t)NB * NH * NW];

__device__ __forceinline__ float2 cadd(float2 a, float2 b){ return make_float2(a.x+b.x, a.y+b.y); }
__device__ __forceinline__ float2 csub(float2 a, float2 b){ return make_float2(a.x-b.x, a.y-b.y); }
__device__ __forceinline__ float2 cmul(float2 a, float2 b){
    return make_float2(fmaf(a.x, b.x, -a.y*b.y), fmaf(a.x, b.y, a.y*b.x));
}
template<int SIGN>
__device__ __forceinline__ float2 rot90(float2 a){   // × (-i) fwd, (+i) inv
    return (SIGN < 0) ? make_float2(a.y, -a.x) : make_float2(-a.y, a.x);
}
template<int SIGN>
__device__ __forceinline__ float2 cmulw(float2 a, float wr, float wi_f){
    float wi = (SIGN < 0) ? wi_f : -wi_f;
    return make_float2(fmaf(a.x, wr, -a.y*wi), fmaf(a.x, wi, a.y*wr));
}
__device__ __forceinline__ __half2 f2h(float2 v){ return __float22half2_rn(v); }
__device__ __forceinline__ float2 h2f(__half2 v){ return __half22float2(v); }

// Fully-unrolled 16-point DFT in registers, all twiddles as immediates.
template<int SIGN>
__device__ __forceinline__ void fft16(float2* r){
    const float C1 = 0.92387953251f, S1 = 0.38268343236f, C2 = 0.70710678119f;
    float2 v[16];
#pragma unroll
    for (int p = 0; p < 4; ++p){
        float2 a=r[p], b=r[p+4], c=r[p+8], d=r[p+12];
        float2 t0=cadd(a,c), t1=csub(a,c), t2=cadd(b,d);
        float2 t3=rot90<SIGN>(csub(b,d));
        float2 u0=cadd(t0,t2), u1=cadd(t1,t3), u2=csub(t0,t2), u3=csub(t1,t3);
        if (p == 1){
            u1 = cmulw<SIGN>(u1,  C1, -S1);
            u2 = cmulw<SIGN>(u2,  C2, -C2);
            u3 = cmulw<SIGN>(u3,  S1, -C1);
        } else if (p == 2){
            u1 = cmulw<SIGN>(u1,  C2, -C2);
            u2 = rot90<SIGN>(u2);
            u3 = cmulw<SIGN>(u3, -C2, -C2);
        } else if (p == 3){
            u1 = cmulw<SIGN>(u1,  S1, -C1);
            u2 = cmulw<SIGN>(u2, -C2, -C2);
            u3 = cmulw<SIGN>(u3, -C1,  S1);
        }
        v[p]=u0; v[4+p]=u1; v[8+p]=u2; v[12+p]=u3;
    }
#pragma unroll
    for (int m = 0; m < 4; ++m){
        float2 a=v[4*m], b=v[4*m+1], c=v[4*m+2], d=v[4*m+3];
        float2 t0=cadd(a,c), t1=csub(a,c), t2=cadd(b,d);
        float2 t3=rot90<SIGN>(csub(b,d));
        r[m]    = cadd(t0,t2);
        r[4+m]  = cadd(t1,t3);
        r[8+m]  = csub(t0,t2);
        r[12+m] = csub(t1,t3);
    }
}

// r[k] *= w^k, w = exp(SIGN*2*pi*i*n1/256). MUFU base + serial power chain.
template<int SIGN>
__device__ __forceinline__ void twiddle_pows(float2* r, int n1){
    float sn, cs;
    __sincosf((float)n1 * 0.024543692606170259f /* pi/128 */, &sn, &cs);
    float2 w = make_float2(cs, (SIGN < 0) ? -sn : sn);
    float2 acc = w;
    r[1] = cmul(r[1], acc);
#pragma unroll
    for (int k = 2; k < 16; ++k){
        acc = cmul(acc, w);
        r[k] = cmul(r[k], acc);
    }
}

// ---------------------------------------------------------------------------
// Pass 1: forward FFT along W with two-for-one real packing.
// 32 rows/block (16 pairs), 256 threads; pair pl = t>>4, n1 = t&15.
// z = x_even + i*x_odd -> one 256-pt FFT -> unpack both spectra.
// ---------------------------------------------------------------------------
__global__ void __launch_bounds__(256) k_rowfft(const float* __restrict__ x){
    __shared__ float2 s[16*GS];
    int t = threadIdx.x;
    int n1 = t & 15, pl = t >> 4;
    int row0 = blockIdx.x * 32;
    const float* xe = x + (size_t)(row0 + 2*pl) * NW;
    const float* xo = xe + NW;
    float2 r[16];
#pragma unroll
    for (int n2 = 0; n2 < 16; ++n2)
        r[n2] = make_float2(xe[n1 + 16*n2], xo[n1 + 16*n2]);
    fft16<-1>(r);                         // over n2 -> regs k2
    twiddle_pows<-1>(r, n1);
    float2* sg = s + pl*GS;
#pragma unroll
    for (int k2 = 0; k2 < 16; ++k2) sg[n1*17 + k2] = r[k2];
    __syncwarp();
#pragma unroll
    for (int i = 0; i < 16; ++i) r[i] = sg[i*17 + n1];   // thread role: k2 = n1
    fft16<-1>(r);                         // over n1 -> regs k1: Z[16*k1 + n1]
    // restage Z for the k <-> 256-k mirror exchange (layout [k1][n1])
    __syncwarp();
#pragma unroll
    for (int k1 = 0; k1 < 16; ++k1) sg[k1*17 + n1] = r[k1];
    __syncwarp();
    __half2* ge = g_scratch + (size_t)(row0 + 2*pl) * NW;
    __half2* go = ge + NW;
    int n1m = (16 - n1) & 15;             // mirror lane (0 -> 0)
#pragma unroll
    for (int k1 = 0; k1 < 16; ++k1){
        int kw = 16*k1 + n1;
        int k1m = (n1 == 0) ? ((16 - k1) & 15) : (15 - k1);
        float2 Z  = r[k1];
        float2 Zm = sg[k1m*17 + n1m];     // Z[(256-kw) mod 256]
        // X_even = (Z + conj(Zm))/2 ; X_odd = -i(Z - conj(Zm))/2
        float2 A = make_float2(0.5f*(Z.x + Zm.x), 0.5f*(Z.y - Zm.y));
        float2 B = make_float2(0.5f*(Z.y + Zm.y), 0.5f*(Zm.x - Z.x));
        ge[kw] = f2h(A);
        go[kw] = f2h(B);
    }
}

// ---------------------------------------------------------------------------
// Pass 2: fwd FFT along H + mask (fftshift folded) + inv FFT along H (×1/256),
// fused, in-place. Block = (batch b, 16-column tile). thread: w = t&15, u = t>>4.
// ---------------------------------------------------------------------------
__global__ void __launch_bounds__(256) k_colfft_mask(const float* __restrict__ pi,
                                                     const int* __restrict__ cid){
    __shared__ float2 s[16*GS];
    __shared__ float sPI[NC];
    int t = threadIdx.x;
    int b  = blockIdx.y;
    int w0 = blockIdx.x * 16;
    if (t < NC) sPI[t] = pi[((b + 64) & 127) * NC + t];
    int w = t & 15, u = t >> 4;
    __half2* g = g_scratch + (size_t)b * NH * NW + w0;
    float2 r[16];
#pragma unroll
    for (int n2 = 0; n2 < 16; ++n2) r[n2] = h2f(g[(u + 16*n2)*NW + w]);
    // hoisted cid loads
    int wp = (w0 + w + 128) & 255;
    int cc[16];
#pragma unroll
    for (int k1 = 0; k1 < 16; ++k1){
        int hp = (16*k1 + u + 128) & 255;
        cc[k1] = __ldg(&cid[hp*NW + wp]);
    }
    fft16<-1>(r);                         // over n2 -> k2
    twiddle_pows<-1>(r, u);
    float2* sg = s + w*GS;
#pragma unroll
    for (int k2 = 0; k2 < 16; ++k2) sg[u*17 + k2] = r[k2];
    __syncthreads();                      // also covers sPI writes
#pragma unroll
    for (int i = 0; i < 16; ++i) r[i] = sg[i*17 + u];    // thread role: k2 = u
    fft16<-1>(r);                         // over n1 -> k1: F[16*k1 + u]
#pragma unroll
    for (int k1 = 0; k1 < 16; ++k1){
        float m = (cc[k1] < NC) ? sPI[cc[k1]] : 1.0f;
        r[k1].x *= m; r[k1].y *= m;
    }
    fft16<1>(r);                          // over k1 -> m1
    twiddle_pows<1>(r, u);
    __syncthreads();
#pragma unroll
    for (int m1 = 0; m1 < 16; ++m1) sg[u*17 + m1] = r[m1];
    __syncthreads();
#pragma unroll
    for (int i = 0; i < 16; ++i) r[i] = sg[i*17 + u];    // thread role: m1 = u
    fft16<1>(r);                          // over k2 -> m2: y[m1 + 16*m2]
    const float inv256 = 1.0f / 256.0f;
#pragma unroll
    for (int m2 = 0; m2 < 16; ++m2)
        g[(u + 16*m2)*NW + w] = f2h(make_float2(r[m2].x * inv256, r[m2].y * inv256));
}

// ---------------------------------------------------------------------------
// Pass 3: inverse FFT along W (remaining 1/256) + magnitude + 3 channels + pi.
// ---------------------------------------------------------------------------
__global__ void __launch_bounds__(256) k_irow_out(const float* __restrict__ x,
                                                  const float* __restrict__ pi,
                                                  float* __restrict__ out){
    __shared__ float2 s[16*GS];
    int t = threadIdx.x;
    int u = t & 15, rl = t >> 4;
    int row = blockIdx.x * 16 + rl;
    int b = row >> 8, h = row & 255;
    const __half2* gp = g_scratch + (size_t)row * NW;
    float2 r[16];
#pragma unroll
    for (int k1 = 0; k1 < 16; ++k1) r[k1] = h2f(gp[u + 16*k1]);
    fft16<1>(r);                          // over k1 -> m1
    twiddle_pows<1>(r, u);
    float2* sg = s + rl*GS;
#pragma unroll
    for (int m1 = 0; m1 < 16; ++m1) sg[u*17 + m1] = r[m1];
    __syncwarp();
#pragma unroll
    for (int i = 0; i < 16; ++i) r[i] = sg[i*17 + u];    // thread role: m1 = u
    fft16<1>(r);                          // over k2 -> m2: y[u + 16*m2]
    const float sc = 1.0f / 256.0f;       // second half of 1/65536
    const float* xr = x + (size_t)row * NW;
    size_t base = ((size_t)(b*3) * NH + h) * NW;
#pragma unroll
    for (int m2 = 0; m2 < 16; ++m2){
        int m = u + 16*m2;
        float2 v = r[m2];
        float mag = sqrtf(fmaf(v.x, v.x, v.y*v.y)) * sc;
        float xv = xr[m];
        out[base + m]                      = xv;
        out[base + (size_t)NH*NW + m]      = mag;
        out[base + 2*(size_t)NH*NW + m]    = fabsf(mag - xv);
    }
    if (blockIdx.x == 0){
        for (int i = t; i < NB * NC; i += 256)
            out[(size_t)NB * 3 * NH * NW + i] = pi[i];
    }
}

extern "C" void kernel_launch(void* const* d_in, const int* in_sizes, int n_in,
                              void* d_out, int out_size) {
    const float* x  = (const float*)d_in[0];   // [128,256,256] f32
    const float* pi = (const float*)d_in[1];   // [128,64]      f32
    const int* cid  = (const int*)d_in[2];     // [256,256]     i32
    float* out = (float*)d_out;                // [128,3,256,256] + [128,64]

    k_rowfft<<<(NB*NH)/32, 256>>>(x);
    k_colfft_mask<<<dim3(NW/16, NB), 256>>>(pi, cid);
    k_irow_out<<<(NB*NH)/16, 256>>>(x, pi, out);
}